// round 7
// baseline (speedup 1.0000x reference)
#include <cuda_runtime.h>
#include <cuda_fp16.h>
#include <cstdint>

#define TOK   8192
#define HDIM  1024
#define FDIM  4096
#define NE    8
#define NCTA  296   // 148 SMs x 2 CTAs

// ---------------- scratch (static device globals) ---------------------------
__device__ int    g_counts[NE];
__device__ int    g_offsets[NE + 1];
__device__ int    g_cursor[NE];
__device__ int    g_topk_i[TOK * 2];
__device__ float  g_topk_w[TOK * 2];
__device__ int    g_list[TOK * 2];
__device__ int    g_rt_e[NE * 64];      // expert id per row-tile
__device__ int    g_rt_row0[NE * 64];   // starting row per row-tile
__device__ int    g_total1, g_total2;   // total work items per GEMM
__device__ int    g_ctr1, g_ctr2;       // persistent work counters
__device__ __half g_xh[(size_t)TOK * HDIM];
__device__ __half g_w1h[(size_t)NE * HDIM * FDIM];
__device__ __half g_w2h[(size_t)NE * FDIM * HDIM];
__device__ __half g_hidh[(size_t)TOK * 2 * FDIM];
__device__ float  g_contrib[(size_t)TOK * 2 * HDIM];

// ---------------- PTX helpers ------------------------------------------------
__device__ __forceinline__ uint32_t smem_u32(const void* p) {
    uint32_t a;
    asm("{ .reg .u64 t; cvta.to.shared.u64 t, %1; cvt.u32.u64 %0, t; }" : "=r"(a) : "l"(p));
    return a;
}
__device__ __forceinline__ void cp16(uint32_t dst, const void* src, int bytes) {
    asm volatile("cp.async.cg.shared.global [%0], [%1], 16, %2;"
                 :: "r"(dst), "l"(src), "r"(bytes));
}
__device__ __forceinline__ void ldsm4(uint32_t* r, uint32_t addr) {
    asm volatile("ldmatrix.sync.aligned.m8n8.x4.shared.b16 {%0,%1,%2,%3}, [%4];"
                 : "=r"(r[0]), "=r"(r[1]), "=r"(r[2]), "=r"(r[3]) : "r"(addr));
}
__device__ __forceinline__ void ldsm4t(uint32_t* r, uint32_t addr) {
    asm volatile("ldmatrix.sync.aligned.m8n8.x4.trans.shared.b16 {%0,%1,%2,%3}, [%4];"
                 : "=r"(r[0]), "=r"(r[1]), "=r"(r[2]), "=r"(r[3]) : "r"(addr));
}
__device__ __forceinline__ void mma_f16(float* d, const uint32_t* a, const uint32_t* b) {
    asm volatile(
        "mma.sync.aligned.m16n8k16.row.col.f32.f16.f16.f32 "
        "{%0,%1,%2,%3}, {%4,%5,%6,%7}, {%8,%9}, {%0,%1,%2,%3};"
        : "+f"(d[0]), "+f"(d[1]), "+f"(d[2]), "+f"(d[3])
        : "r"(a[0]), "r"(a[1]), "r"(a[2]), "r"(a[3]), "r"(b[0]), "r"(b[1]));
}
__device__ __forceinline__ float gelu_exact(float v) {
    return 0.5f * v * (1.0f + erff(v * 0.70710678118654752f));
}

// ---------------- small kernels ----------------------------------------------
__global__ void reset_kernel() {
    if (threadIdx.x < NE) g_counts[threadIdx.x] = 0;
}

__global__ void cvt_half_kernel(const float* __restrict__ src, __half* __restrict__ dst,
                                size_t n8) {
    size_t i = (size_t)blockIdx.x * blockDim.x + threadIdx.x;
    if (i < n8) {
        float4 v0 = ((const float4*)src)[i * 2];
        float4 v1 = ((const float4*)src)[i * 2 + 1];
        __half2 h[4];
        h[0] = __floats2half2_rn(v0.x, v0.y);
        h[1] = __floats2half2_rn(v0.z, v0.w);
        h[2] = __floats2half2_rn(v1.x, v1.y);
        h[3] = __floats2half2_rn(v1.z, v1.w);
        ((uint4*)dst)[i] = *(uint4*)h;
    }
}

__global__ void router_kernel(const float* __restrict__ x, const float* __restrict__ rw) {
    __shared__ float srw[NE * HDIM];
    int tid = threadIdx.x;
    for (int i = tid; i < NE * HDIM; i += 256) srw[i] = rw[i];
    __syncthreads();
    int warp = tid >> 5, lane = tid & 31;
    int t = blockIdx.x * 8 + warp;
    if (t >= TOK) return;
    const float* xr = x + (size_t)t * HDIM;
    float acc[NE];
#pragma unroll
    for (int e = 0; e < NE; e++) acc[e] = 0.0f;
    for (int h = lane; h < HDIM; h += 32) {
        float xv = xr[h];
#pragma unroll
        for (int e = 0; e < NE; e++) acc[e] += xv * srw[e * HDIM + h];
    }
#pragma unroll
    for (int off = 16; off > 0; off >>= 1)
#pragma unroll
        for (int e = 0; e < NE; e++) acc[e] += __shfl_xor_sync(0xffffffffu, acc[e], off);
    if (lane == 0) {
        float mx = acc[0];
#pragma unroll
        for (int e = 1; e < NE; e++) mx = fmaxf(mx, acc[e]);
        float p[NE], s = 0.0f;
#pragma unroll
        for (int e = 0; e < NE; e++) { p[e] = expf(acc[e] - mx); s += p[e]; }
        float inv = 1.0f / s;
#pragma unroll
        for (int e = 0; e < NE; e++) p[e] *= inv;
        int i1 = 0;
#pragma unroll
        for (int e = 1; e < NE; e++) if (p[e] > p[i1]) i1 = e;
        int i2 = (i1 == 0) ? 1 : 0;
#pragma unroll
        for (int e = 0; e < NE; e++) if (e != i1 && p[e] > p[i2]) i2 = e;
        g_topk_i[t * 2 + 0] = i1; g_topk_w[t * 2 + 0] = p[i1];
        g_topk_i[t * 2 + 1] = i2; g_topk_w[t * 2 + 1] = p[i2];
        atomicAdd(&g_counts[i1], 1);
        atomicAdd(&g_counts[i2], 1);
    }
}

// scan + build dense row-tile work list + reset persistent counters
__global__ void scan_kernel() {
    if (threadIdx.x == 0) {
        int o = 0, nrt = 0;
        g_offsets[0] = 0;
        for (int e = 0; e < NE; e++) {
            g_cursor[e] = o;
            int cnt = g_counts[e];
            int r0 = o;
            o += cnt;
            g_offsets[e + 1] = o;
            for (int r = r0; r < o; r += 128) {
                g_rt_e[nrt] = e;
                g_rt_row0[nrt] = r;
                nrt++;
            }
        }
        g_total1 = nrt * (FDIM / 128);
        g_total2 = nrt * (HDIM / 128);
        g_ctr1 = 0;
        g_ctr2 = 0;
    }
}

__global__ void scatter_kernel() {
    int t = blockIdx.x * 256 + threadIdx.x;
    if (t < TOK) {
#pragma unroll
        for (int s = 0; s < 2; s++) {
            int e = g_topk_i[t * 2 + s];
            int pos = atomicAdd(&g_cursor[e], 1);
            g_list[pos] = t * 2 + s;
        }
    }
}

// ---------------- persistent fp16 grouped GEMM --------------------------------
// Tile 128x128, BK=64, 128 threads = 4 warps (2Mx2N), warp tile 64x64.
// 3-stage cp.async pipeline (wait_group 1/0 — stage kt MUST be complete),
// 2 CTAs/SM, atomic work queue over (row-tile, n-tile) items.
template <int KD, int ND, bool FFN1>
__global__ void __launch_bounds__(128, 2)
moe_gemm_h(const __half* __restrict__ Ah, const __half* __restrict__ Wh,
           const float* __restrict__ bias) {
    extern __shared__ char smem[];
    __shared__ int s_id;
    uint32_t smb = smem_u32(smem);

    int tid = threadIdx.x;
    int warp = tid >> 5, lane = tid & 31;
    int wm = warp & 1, wn = warp >> 1;
    int l15 = lane & 15, hi = lane >> 4;
    int r4 = lane >> 2, c2 = (lane & 3) * 2;

    constexpr int NT = ND / 128;
    const int total = FFN1 ? g_total1 : g_total2;
    int* ctr = FFN1 ? &g_ctr1 : &g_ctr2;

    while (true) {
        if (tid == 0) s_id = atomicAdd(ctr, 1);
        __syncthreads();            // broadcast id
        int id = s_id;
        __syncthreads();            // all reads done before next tile's write
        if (id >= total) return;

        int rtg = id / NT, nt = id % NT;
        int e = g_rt_e[rtg];
        int row0 = g_rt_row0[rtg];
        int seg1 = g_offsets[e + 1];
        int n0 = nt * 128;

        // ---- A loader: 8 chunks/thread ----
        const __half* a_src[8];
        int a_bytes[8];
#pragma unroll
        for (int j = 0; j < 8; j++) {
            int idx = tid + 128 * j;
            int row = idx >> 3, c = idx & 7;
            int grow = row0 + row;
            bool v = grow < seg1;
            if (FFN1) {
                int pair = v ? g_list[grow] : 0;
                a_src[j] = Ah + (size_t)(pair >> 1) * KD + c * 8;
            } else {
                a_src[j] = Ah + (size_t)(v ? grow : row0) * KD + c * 8;
            }
            a_bytes[j] = v ? 16 : 0;
        }
        const __half* wbase = Wh + (size_t)e * KD * ND + n0;

        auto load_stage = [&](int s, int kt) {
            int k0 = kt * 64;
            uint32_t base = smb + s * 32768;
#pragma unroll
            for (int j = 0; j < 8; j++) {
                int idx = tid + 128 * j;
                int row = idx >> 3, c = idx & 7;
                uint32_t off = (uint32_t)row * 128 + (uint32_t)((c ^ (row & 7)) << 4);
                cp16(base + off, a_src[j] + k0, a_bytes[j]);
            }
#pragma unroll
            for (int j = 0; j < 8; j++) {
                int idx = tid + 128 * j;
                int k = idx >> 4, c = idx & 15;
                uint32_t off = 16384u + (uint32_t)k * 256 + (uint32_t)((c ^ (k & 7)) << 4);
                cp16(base + off, wbase + (size_t)(k0 + k) * ND + c * 8, 16);
            }
            asm volatile("cp.async.commit_group;");
        };

        float acc[4][8][4];
#pragma unroll
        for (int mi = 0; mi < 4; mi++)
#pragma unroll
            for (int ni = 0; ni < 8; ni++)
#pragma unroll
                for (int d = 0; d < 4; d++) acc[mi][ni][d] = 0.0f;

        constexpr int KT = KD / 64;
        load_stage(0, 0);
        load_stage(1, 1);

        for (int kt = 0; kt < KT; kt++) {
            if (kt + 1 < KT) asm volatile("cp.async.wait_group 1;");
            else             asm volatile("cp.async.wait_group 0;");
            __syncthreads();
            if (kt + 2 < KT) load_stage((kt + 2) % 3, kt + 2);

            uint32_t abase = smb + (kt % 3) * 32768;
            uint32_t bbase = abase + 16384;
#pragma unroll
            for (int ks = 0; ks < 4; ks++) {
                uint32_t a[4][4];
#pragma unroll
                for (int mi = 0; mi < 4; mi++) {
                    int row = wm * 64 + mi * 16 + l15;
                    uint32_t addr = abase + (uint32_t)row * 128 +
                                    (uint32_t)(((ks * 2 + hi) ^ (row & 7)) << 4);
                    ldsm4(a[mi], addr);
                }
                uint32_t b[4][4];
#pragma unroll
                for (int np = 0; np < 4; np++) {
                    int krow = ks * 16 + l15;
                    int c = wn * 8 + np * 2 + hi;
                    uint32_t addr = bbase + (uint32_t)krow * 256 +
                                    (uint32_t)((c ^ (krow & 7)) << 4);
                    ldsm4t(b[np], addr);
                }
#pragma unroll
                for (int mi = 0; mi < 4; mi++)
#pragma unroll
                    for (int np = 0; np < 4; np++) {
                        mma_f16(acc[mi][np * 2 + 0], a[mi], b[np] + 0);
                        mma_f16(acc[mi][np * 2 + 1], a[mi], b[np] + 2);
                    }
            }
        }

        // ---- epilogue ----
#pragma unroll
        for (int mi = 0; mi < 4; mi++) {
#pragma unroll
            for (int h = 0; h < 2; h++) {
                int grow = row0 + wm * 64 + mi * 16 + r4 + h * 8;
                if (grow < seg1) {
                    if (FFN1) {
                        __half* orow = g_hidh + (size_t)grow * ND;
#pragma unroll
                        for (int ni = 0; ni < 8; ni++) {
                            int col = n0 + wn * 64 + ni * 8 + c2;
                            float2 bv = *(const float2*)(bias + (size_t)e * ND + col);
                            float v0 = gelu_exact(acc[mi][ni][h * 2 + 0] + bv.x);
                            float v1 = gelu_exact(acc[mi][ni][h * 2 + 1] + bv.y);
                            *(__half2*)(orow + col) = __floats2half2_rn(v0, v1);
                        }
                    } else {
                        int pair = g_list[grow];
                        float wgt = g_topk_w[pair];
                        float* orow = g_contrib + (size_t)pair * ND;
#pragma unroll
                        for (int ni = 0; ni < 8; ni++) {
                            int col = n0 + wn * 64 + ni * 8 + c2;
                            float2 bv = *(const float2*)(bias + (size_t)e * ND + col);
                            float v0 = (acc[mi][ni][h * 2 + 0] + bv.x) * wgt;
                            float v1 = (acc[mi][ni][h * 2 + 1] + bv.y) * wgt;
                            *(float2*)(orow + col) = make_float2(v0, v1);
                        }
                    }
                }
            }
        }
    }
}

// ---------------- combine -----------------------------------------------------
__global__ void combine_kernel(float* __restrict__ out) {
    constexpr int H4 = HDIM / 4;
    size_t i = (size_t)blockIdx.x * blockDim.x + threadIdx.x;
    if (i < (size_t)TOK * H4) {
        size_t t = i / H4, h4 = i % H4;
        const float4* c = (const float4*)g_contrib;
        float4 a = c[(t * 2) * H4 + h4];
        float4 b = c[(t * 2 + 1) * H4 + h4];
        ((float4*)out)[i] = make_float4(a.x + b.x, a.y + b.y, a.z + b.z, a.w + b.w);
    }
}

// ---------------- launch --------------------------------------------------------
extern "C" void kernel_launch(void* const* d_in, const int* in_sizes, int n_in,
                              void* d_out, int out_size) {
    const float* x  = (const float*)d_in[0];
    const float* rw = (const float*)d_in[1];
    const float* w1 = (const float*)d_in[2];
    const float* b1 = (const float*)d_in[3];
    const float* w2 = (const float*)d_in[4];
    const float* b2 = (const float*)d_in[5];
    float* out = (float*)d_out;

    __half* xh;  cudaGetSymbolAddress((void**)&xh,  g_xh);
    __half* w1h; cudaGetSymbolAddress((void**)&w1h, g_w1h);
    __half* w2h; cudaGetSymbolAddress((void**)&w2h, g_w2h);
    __half* hid; cudaGetSymbolAddress((void**)&hid, g_hidh);

    constexpr int SMEM_BYTES = 3 * 32768;  // 98304
    cudaFuncSetAttribute(moe_gemm_h<HDIM, FDIM, true >,
                         cudaFuncAttributeMaxDynamicSharedMemorySize, SMEM_BYTES);
    cudaFuncSetAttribute(moe_gemm_h<FDIM, HDIM, false>,
                         cudaFuncAttributeMaxDynamicSharedMemorySize, SMEM_BYTES);

    reset_kernel<<<1, 32>>>();
    router_kernel<<<TOK / 8, 256>>>(x, rw);
    scan_kernel<<<1, 32>>>();
    scatter_kernel<<<TOK / 256, 256>>>();

    size_t nx  = (size_t)TOK * HDIM / 8;
    size_t nw1 = (size_t)NE * HDIM * FDIM / 8;
    size_t nw2 = (size_t)NE * FDIM * HDIM / 8;
    cvt_half_kernel<<<(int)((nx  + 255) / 256), 256>>>(x,  xh,  nx);
    cvt_half_kernel<<<(int)((nw1 + 255) / 256), 256>>>(w1, w1h, nw1);
    cvt_half_kernel<<<(int)((nw2 + 255) / 256), 256>>>(w2, w2h, nw2);

    moe_gemm_h<HDIM, FDIM, true ><<<NCTA, 128, SMEM_BYTES>>>(xh,  w1h, b1);
    moe_gemm_h<FDIM, HDIM, false><<<NCTA, 128, SMEM_BYTES>>>(hid, w2h, b2);
    combine_kernel<<<(TOK * HDIM / 4) / 256, 256>>>(out);
}

// round 8
// speedup vs baseline: 1.1532x; 1.1532x over previous
#include <cuda_runtime.h>
#include <cuda_fp16.h>
#include <cstdint>

#define TOK   8192
#define HDIM  1024
#define FDIM  4096
#define NE    8

// ---------------- scratch (static device globals) ---------------------------
__device__ int    g_counts[NE];
__device__ int    g_offsets[NE + 1];
__device__ int    g_cursor[NE];
__device__ int    g_topk_i[TOK * 2];
__device__ float  g_topk_w[TOK * 2];
__device__ int    g_list[TOK * 2];
__device__ __half g_xh[(size_t)TOK * HDIM];            // x in fp16
__device__ __half g_w1h[(size_t)NE * HDIM * FDIM];     // w1 in fp16
__device__ __half g_w2h[(size_t)NE * FDIM * HDIM];     // w2 in fp16
__device__ __half g_hidh[(size_t)TOK * 2 * FDIM];      // gelu(x@w1+b1) fp16
__device__ float  g_contrib[(size_t)TOK * 2 * HDIM];   // fp32 weighted expert out

// ---------------- PTX helpers ------------------------------------------------
__device__ __forceinline__ uint32_t smem_u32(const void* p) {
    uint32_t a;
    asm("{ .reg .u64 t; cvta.to.shared.u64 t, %1; cvt.u32.u64 %0, t; }" : "=r"(a) : "l"(p));
    return a;
}
__device__ __forceinline__ void cp16(uint32_t dst, const void* src, int bytes) {
    asm volatile("cp.async.cg.shared.global [%0], [%1], 16, %2;"
                 :: "r"(dst), "l"(src), "r"(bytes));
}
__device__ __forceinline__ void ldsm4(uint32_t* r, uint32_t addr) {
    asm volatile("ldmatrix.sync.aligned.m8n8.x4.shared.b16 {%0,%1,%2,%3}, [%4];"
                 : "=r"(r[0]), "=r"(r[1]), "=r"(r[2]), "=r"(r[3]) : "r"(addr));
}
__device__ __forceinline__ void ldsm4t(uint32_t* r, uint32_t addr) {
    asm volatile("ldmatrix.sync.aligned.m8n8.x4.trans.shared.b16 {%0,%1,%2,%3}, [%4];"
                 : "=r"(r[0]), "=r"(r[1]), "=r"(r[2]), "=r"(r[3]) : "r"(addr));
}
__device__ __forceinline__ void mma_f16(float* d, const uint32_t* a, const uint32_t* b) {
    asm volatile(
        "mma.sync.aligned.m16n8k16.row.col.f32.f16.f16.f32 "
        "{%0,%1,%2,%3}, {%4,%5,%6,%7}, {%8,%9}, {%0,%1,%2,%3};"
        : "+f"(d[0]), "+f"(d[1]), "+f"(d[2]), "+f"(d[3])
        : "r"(a[0]), "r"(a[1]), "r"(a[2]), "r"(a[3]), "r"(b[0]), "r"(b[1]));
}
__device__ __forceinline__ float gelu_exact(float v) {
    return 0.5f * v * (1.0f + erff(v * 0.70710678118654752f));
}

// ---------------- small kernels ----------------------------------------------
__global__ void reset_kernel() {
    if (threadIdx.x < NE) g_counts[threadIdx.x] = 0;
}

__global__ void cvt_half_kernel(const float* __restrict__ src, __half* __restrict__ dst,
                                size_t n8) {
    size_t i = (size_t)blockIdx.x * blockDim.x + threadIdx.x;
    if (i < n8) {
        float4 v0 = ((const float4*)src)[i * 2];
        float4 v1 = ((const float4*)src)[i * 2 + 1];
        __half2 h[4];
        h[0] = __floats2half2_rn(v0.x, v0.y);
        h[1] = __floats2half2_rn(v0.z, v0.w);
        h[2] = __floats2half2_rn(v1.x, v1.y);
        h[3] = __floats2half2_rn(v1.z, v1.w);
        ((uint4*)dst)[i] = *(uint4*)h;
    }
}

__global__ void router_kernel(const float* __restrict__ x, const float* __restrict__ rw) {
    __shared__ float srw[NE * HDIM];
    int tid = threadIdx.x;
    for (int i = tid; i < NE * HDIM; i += 256) srw[i] = rw[i];
    __syncthreads();
    int warp = tid >> 5, lane = tid & 31;
    int t = blockIdx.x * 8 + warp;
    if (t >= TOK) return;
    const float* xr = x + (size_t)t * HDIM;
    float acc[NE];
#pragma unroll
    for (int e = 0; e < NE; e++) acc[e] = 0.0f;
    for (int h = lane; h < HDIM; h += 32) {
        float xv = xr[h];
#pragma unroll
        for (int e = 0; e < NE; e++) acc[e] += xv * srw[e * HDIM + h];
    }
#pragma unroll
    for (int off = 16; off > 0; off >>= 1)
#pragma unroll
        for (int e = 0; e < NE; e++) acc[e] += __shfl_xor_sync(0xffffffffu, acc[e], off);
    if (lane == 0) {
        float mx = acc[0];
#pragma unroll
        for (int e = 1; e < NE; e++) mx = fmaxf(mx, acc[e]);
        float p[NE], s = 0.0f;
#pragma unroll
        for (int e = 0; e < NE; e++) { p[e] = expf(acc[e] - mx); s += p[e]; }
        float inv = 1.0f / s;
#pragma unroll
        for (int e = 0; e < NE; e++) p[e] *= inv;
        int i1 = 0;
#pragma unroll
        for (int e = 1; e < NE; e++) if (p[e] > p[i1]) i1 = e;
        int i2 = (i1 == 0) ? 1 : 0;
#pragma unroll
        for (int e = 0; e < NE; e++) if (e != i1 && p[e] > p[i2]) i2 = e;
        g_topk_i[t * 2 + 0] = i1; g_topk_w[t * 2 + 0] = p[i1];
        g_topk_i[t * 2 + 1] = i2; g_topk_w[t * 2 + 1] = p[i2];
        atomicAdd(&g_counts[i1], 1);
        atomicAdd(&g_counts[i2], 1);
    }
}

__global__ void scan_kernel() {
    if (threadIdx.x == 0) {
        int o = 0;
        g_offsets[0] = 0;
        for (int e = 0; e < NE; e++) {
            g_cursor[e] = o;
            o += g_counts[e];
            g_offsets[e + 1] = o;
        }
    }
}

__global__ void scatter_kernel() {
    int t = blockIdx.x * 256 + threadIdx.x;
    if (t < TOK) {
#pragma unroll
        for (int s = 0; s < 2; s++) {
            int e = g_topk_i[t * 2 + s];
            int pos = atomicAdd(&g_cursor[e], 1);
            g_list[pos] = t * 2 + s;
        }
    }
}

// ---------------- fp16 grouped GEMM (m16n8k16 + ldmatrix) --------------------
// Tile 128x128, BK=64, 128 threads = 4 warps (2Mx2N), warp tile 64x64.
// 3-stage cp.async pipeline + register-level fragment double-buffering:
// fragments for ks+1 are LDSM'd before the MMAs of ks are issued.
template <int KD, int ND, bool FFN1>
__global__ void __launch_bounds__(128, 2)
moe_gemm_h(const __half* __restrict__ Ah, const __half* __restrict__ Wh,
           const float* __restrict__ bias) {
    extern __shared__ char smem[];
    uint32_t smb = smem_u32(smem);

    int tid = threadIdx.x;
    int warp = tid >> 5, lane = tid & 31;
    int wm = warp & 1, wn = warp >> 1;
    int l15 = lane & 15, hi = lane >> 4;

    int e = blockIdx.y >> 6;
    int rt = blockIdx.y & 63;
    int seg0 = g_offsets[e], seg1 = g_offsets[e + 1];
    int row0 = seg0 + rt * 128;
    if (row0 >= seg1) return;
    int n0 = blockIdx.x * 128;

    // ---- A loader: 8 chunks/thread ----
    const __half* a_src[8];
    int a_bytes[8];
#pragma unroll
    for (int j = 0; j < 8; j++) {
        int idx = tid + 128 * j;
        int row = idx >> 3, c = idx & 7;
        int grow = row0 + row;
        bool v = grow < seg1;
        if (FFN1) {
            int pair = v ? g_list[grow] : 0;
            a_src[j] = Ah + (size_t)(pair >> 1) * KD + c * 8;
        } else {
            a_src[j] = Ah + (size_t)(v ? grow : row0) * KD + c * 8;
        }
        a_bytes[j] = v ? 16 : 0;
    }
    const __half* wbase = Wh + (size_t)e * KD * ND + n0;

    auto load_stage = [&](int s, int kt) {
        int k0 = kt * 64;
        uint32_t base = smb + s * 32768;
#pragma unroll
        for (int j = 0; j < 8; j++) {
            int idx = tid + 128 * j;
            int row = idx >> 3, c = idx & 7;
            uint32_t off = (uint32_t)row * 128 + (uint32_t)((c ^ (row & 7)) << 4);
            cp16(base + off, a_src[j] + k0, a_bytes[j]);
        }
#pragma unroll
        for (int j = 0; j < 8; j++) {
            int idx = tid + 128 * j;
            int k = idx >> 4, c = idx & 15;
            uint32_t off = 16384u + (uint32_t)k * 256 + (uint32_t)((c ^ (k & 7)) << 4);
            cp16(base + off, wbase + (size_t)(k0 + k) * ND + c * 8, 16);
        }
        asm volatile("cp.async.commit_group;");
    };

    float acc[4][8][4];
#pragma unroll
    for (int mi = 0; mi < 4; mi++)
#pragma unroll
        for (int ni = 0; ni < 8; ni++)
#pragma unroll
            for (int d = 0; d < 4; d++) acc[mi][ni][d] = 0.0f;

    constexpr int KT = KD / 64;
    load_stage(0, 0);
    load_stage(1, 1);

    uint32_t af[2][4][4], bf[2][4][4];

    for (int kt = 0; kt < KT; kt++) {
        if (kt + 1 < KT) asm volatile("cp.async.wait_group 1;");
        else             asm volatile("cp.async.wait_group 0;");
        __syncthreads();
        if (kt + 2 < KT) load_stage((kt + 2) % 3, kt + 2);

        uint32_t abase = smb + (kt % 3) * 32768;
        uint32_t bbase = abase + 16384;

        // fragment loader for one ks step into buffer `buf`
        auto ld_frags = [&](int buf, int ks) {
#pragma unroll
            for (int mi = 0; mi < 4; mi++) {
                int row = wm * 64 + mi * 16 + l15;
                uint32_t addr = abase + (uint32_t)row * 128 +
                                (uint32_t)(((ks * 2 + hi) ^ (row & 7)) << 4);
                ldsm4(af[buf][mi], addr);
            }
#pragma unroll
            for (int np = 0; np < 4; np++) {
                int krow = ks * 16 + l15;
                int c = wn * 8 + np * 2 + hi;
                uint32_t addr = bbase + (uint32_t)krow * 256 +
                                (uint32_t)((c ^ (krow & 7)) << 4);
                ldsm4t(bf[buf][np], addr);
            }
        };

        ld_frags(0, 0);
#pragma unroll
        for (int ks = 0; ks < 4; ks++) {
            int cur = ks & 1;
            if (ks < 3) ld_frags(cur ^ 1, ks + 1);
#pragma unroll
            for (int mi = 0; mi < 4; mi++)
#pragma unroll
                for (int np = 0; np < 4; np++) {
                    mma_f16(acc[mi][np * 2 + 0], af[cur][mi], bf[cur][np] + 0);
                    mma_f16(acc[mi][np * 2 + 1], af[cur][mi], bf[cur][np] + 2);
                }
        }
    }

    // ---- epilogue ----
    int r4 = lane >> 2, c2 = (lane & 3) * 2;
#pragma unroll
    for (int mi = 0; mi < 4; mi++) {
#pragma unroll
        for (int h = 0; h < 2; h++) {
            int grow = row0 + wm * 64 + mi * 16 + r4 + h * 8;
            if (grow < seg1) {
                if (FFN1) {
                    __half* orow = g_hidh + (size_t)grow * ND;
#pragma unroll
                    for (int ni = 0; ni < 8; ni++) {
                        int col = n0 + wn * 64 + ni * 8 + c2;
                        float2 bv = *(const float2*)(bias + (size_t)e * ND + col);
                        float v0 = gelu_exact(acc[mi][ni][h * 2 + 0] + bv.x);
                        float v1 = gelu_exact(acc[mi][ni][h * 2 + 1] + bv.y);
                        *(__half2*)(orow + col) = __floats2half2_rn(v0, v1);
                    }
                } else {
                    int pair = g_list[grow];
                    float wgt = g_topk_w[pair];
                    float* orow = g_contrib + (size_t)pair * ND;
#pragma unroll
                    for (int ni = 0; ni < 8; ni++) {
                        int col = n0 + wn * 64 + ni * 8 + c2;
                        float2 bv = *(const float2*)(bias + (size_t)e * ND + col);
                        float v0 = (acc[mi][ni][h * 2 + 0] + bv.x) * wgt;
                        float v1 = (acc[mi][ni][h * 2 + 1] + bv.y) * wgt;
                        *(float2*)(orow + col) = make_float2(v0, v1);
                    }
                }
            }
        }
    }
}

// ---------------- combine -----------------------------------------------------
__global__ void combine_kernel(float* __restrict__ out) {
    constexpr int H4 = HDIM / 4;
    size_t i = (size_t)blockIdx.x * blockDim.x + threadIdx.x;
    if (i < (size_t)TOK * H4) {
        size_t t = i / H4, h4 = i % H4;
        const float4* c = (const float4*)g_contrib;
        float4 a = c[(t * 2) * H4 + h4];
        float4 b = c[(t * 2 + 1) * H4 + h4];
        ((float4*)out)[i] = make_float4(a.x + b.x, a.y + b.y, a.z + b.z, a.w + b.w);
    }
}

// ---------------- launch --------------------------------------------------------
extern "C" void kernel_launch(void* const* d_in, const int* in_sizes, int n_in,
                              void* d_out, int out_size) {
    const float* x  = (const float*)d_in[0];
    const float* rw = (const float*)d_in[1];
    const float* w1 = (const float*)d_in[2];
    const float* b1 = (const float*)d_in[3];
    const float* w2 = (const float*)d_in[4];
    const float* b2 = (const float*)d_in[5];
    float* out = (float*)d_out;

    __half* xh;  cudaGetSymbolAddress((void**)&xh,  g_xh);
    __half* w1h; cudaGetSymbolAddress((void**)&w1h, g_w1h);
    __half* w2h; cudaGetSymbolAddress((void**)&w2h, g_w2h);
    __half* hid; cudaGetSymbolAddress((void**)&hid, g_hidh);

    constexpr int SMEM_BYTES = 3 * 32768;  // 98304
    cudaFuncSetAttribute(moe_gemm_h<HDIM, FDIM, true >,
                         cudaFuncAttributeMaxDynamicSharedMemorySize, SMEM_BYTES);
    cudaFuncSetAttribute(moe_gemm_h<FDIM, HDIM, false>,
                         cudaFuncAttributeMaxDynamicSharedMemorySize, SMEM_BYTES);

    reset_kernel<<<1, 32>>>();
    router_kernel<<<TOK / 8, 256>>>(x, rw);
    scan_kernel<<<1, 32>>>();
    scatter_kernel<<<TOK / 256, 256>>>();

    size_t nx  = (size_t)TOK * HDIM / 8;
    size_t nw1 = (size_t)NE * HDIM * FDIM / 8;
    size_t nw2 = (size_t)NE * FDIM * HDIM / 8;
    cvt_half_kernel<<<(int)((nx  + 255) / 256), 256>>>(x,  xh,  nx);
    cvt_half_kernel<<<(int)((nw1 + 255) / 256), 256>>>(w1, w1h, nw1);
    cvt_half_kernel<<<(int)((nw2 + 255) / 256), 256>>>(w2, w2h, nw2);

    moe_gemm_h<HDIM, FDIM, true ><<<dim3(FDIM / 128, NE * 64), 128, SMEM_BYTES>>>(xh,  w1h, b1);
    moe_gemm_h<FDIM, HDIM, false><<<dim3(HDIM / 128, NE * 64), 128, SMEM_BYTES>>>(hid, w2h, b2);
    combine_kernel<<<(TOK * HDIM / 4) / 256, 256>>>(out);
}

// round 9
// speedup vs baseline: 1.2149x; 1.0536x over previous
#include <cuda_runtime.h>
#include <cuda_fp16.h>
#include <cstdint>

#define TOK   8192
#define HDIM  1024
#define FDIM  4096
#define NE    8

// ---------------- scratch (static device globals) ---------------------------
__device__ int    g_counts[NE];
__device__ int    g_offsets[NE + 1];
__device__ int    g_cursor[NE];
__device__ int    g_topk_i[TOK * 2];
__device__ float  g_topk_w[TOK * 2];
__device__ int    g_list[TOK * 2];
__device__ __half g_xh[(size_t)TOK * HDIM];            // x in fp16
__device__ __half g_w1h[(size_t)NE * HDIM * FDIM];     // w1 in fp16
__device__ __half g_w2h[(size_t)NE * FDIM * HDIM];     // w2 in fp16
__device__ __half g_hidh[(size_t)TOK * 2 * FDIM];      // gelu(x@w1+b1) fp16
__device__ float  g_contrib[(size_t)TOK * 2 * HDIM];   // fp32 weighted expert out

// ---------------- PTX helpers ------------------------------------------------
__device__ __forceinline__ uint32_t smem_u32(const void* p) {
    uint32_t a;
    asm("{ .reg .u64 t; cvta.to.shared.u64 t, %1; cvt.u32.u64 %0, t; }" : "=r"(a) : "l"(p));
    return a;
}
__device__ __forceinline__ void cp16(uint32_t dst, const void* src, int bytes) {
    asm volatile("cp.async.cg.shared.global [%0], [%1], 16, %2;"
                 :: "r"(dst), "l"(src), "r"(bytes));
}
__device__ __forceinline__ void ldsm4(uint32_t* r, uint32_t addr) {
    asm volatile("ldmatrix.sync.aligned.m8n8.x4.shared.b16 {%0,%1,%2,%3}, [%4];"
                 : "=r"(r[0]), "=r"(r[1]), "=r"(r[2]), "=r"(r[3]) : "r"(addr));
}
__device__ __forceinline__ void ldsm4t(uint32_t* r, uint32_t addr) {
    asm volatile("ldmatrix.sync.aligned.m8n8.x4.trans.shared.b16 {%0,%1,%2,%3}, [%4];"
                 : "=r"(r[0]), "=r"(r[1]), "=r"(r[2]), "=r"(r[3]) : "r"(addr));
}
__device__ __forceinline__ void mma_f16(float* d, const uint32_t* a, const uint32_t* b) {
    asm volatile(
        "mma.sync.aligned.m16n8k16.row.col.f32.f16.f16.f32 "
        "{%0,%1,%2,%3}, {%4,%5,%6,%7}, {%8,%9}, {%0,%1,%2,%3};"
        : "+f"(d[0]), "+f"(d[1]), "+f"(d[2]), "+f"(d[3])
        : "r"(a[0]), "r"(a[1]), "r"(a[2]), "r"(a[3]), "r"(b[0]), "r"(b[1]));
}
__device__ __forceinline__ float gelu_exact(float v) {
    return 0.5f * v * (1.0f + erff(v * 0.70710678118654752f));
}

// ---------------- small kernels ----------------------------------------------
__global__ void reset_kernel() {
    if (threadIdx.x < NE) g_counts[threadIdx.x] = 0;
}

__global__ void cvt_half_kernel(const float* __restrict__ src, __half* __restrict__ dst,
                                size_t n8) {
    size_t i = (size_t)blockIdx.x * blockDim.x + threadIdx.x;
    if (i < n8) {
        float4 v0 = ((const float4*)src)[i * 2];
        float4 v1 = ((const float4*)src)[i * 2 + 1];
        __half2 h[4];
        h[0] = __floats2half2_rn(v0.x, v0.y);
        h[1] = __floats2half2_rn(v0.z, v0.w);
        h[2] = __floats2half2_rn(v1.x, v1.y);
        h[3] = __floats2half2_rn(v1.z, v1.w);
        ((uint4*)dst)[i] = *(uint4*)h;
    }
}

__global__ void router_kernel(const float* __restrict__ x, const float* __restrict__ rw) {
    __shared__ float srw[NE * HDIM];
    int tid = threadIdx.x;
    for (int i = tid; i < NE * HDIM; i += 256) srw[i] = rw[i];
    __syncthreads();
    int warp = tid >> 5, lane = tid & 31;
    int t = blockIdx.x * 8 + warp;
    if (t >= TOK) return;
    const float* xr = x + (size_t)t * HDIM;
    float acc[NE];
#pragma unroll
    for (int e = 0; e < NE; e++) acc[e] = 0.0f;
    for (int h = lane; h < HDIM; h += 32) {
        float xv = xr[h];
#pragma unroll
        for (int e = 0; e < NE; e++) acc[e] += xv * srw[e * HDIM + h];
    }
#pragma unroll
    for (int off = 16; off > 0; off >>= 1)
#pragma unroll
        for (int e = 0; e < NE; e++) acc[e] += __shfl_xor_sync(0xffffffffu, acc[e], off);
    if (lane == 0) {
        float mx = acc[0];
#pragma unroll
        for (int e = 1; e < NE; e++) mx = fmaxf(mx, acc[e]);
        float p[NE], s = 0.0f;
#pragma unroll
        for (int e = 0; e < NE; e++) { p[e] = expf(acc[e] - mx); s += p[e]; }
        float inv = 1.0f / s;
#pragma unroll
        for (int e = 0; e < NE; e++) p[e] *= inv;
        int i1 = 0;
#pragma unroll
        for (int e = 1; e < NE; e++) if (p[e] > p[i1]) i1 = e;
        int i2 = (i1 == 0) ? 1 : 0;
#pragma unroll
        for (int e = 0; e < NE; e++) if (e != i1 && p[e] > p[i2]) i2 = e;
        g_topk_i[t * 2 + 0] = i1; g_topk_w[t * 2 + 0] = p[i1];
        g_topk_i[t * 2 + 1] = i2; g_topk_w[t * 2 + 1] = p[i2];
        atomicAdd(&g_counts[i1], 1);
        atomicAdd(&g_counts[i2], 1);
    }
}

__global__ void scan_kernel() {
    if (threadIdx.x == 0) {
        int o = 0;
        g_offsets[0] = 0;
        for (int e = 0; e < NE; e++) {
            g_cursor[e] = o;
            o += g_counts[e];
            g_offsets[e + 1] = o;
        }
    }
}

__global__ void scatter_kernel() {
    int t = blockIdx.x * 256 + threadIdx.x;
    if (t < TOK) {
#pragma unroll
        for (int s = 0; s < 2; s++) {
            int e = g_topk_i[t * 2 + s];
            int pos = atomicAdd(&g_cursor[e], 1);
            g_list[pos] = t * 2 + s;
        }
    }
}

// ---------------- fp16 grouped GEMM (m16n8k16 + ldmatrix) --------------------
// Tile 128x128, BK=64, 128 threads = 4 warps (2Mx2N), warp tile 64x64.
// 3-stage cp.async pipeline, one __syncthreads per K-tile. (R4 hot loop.)
template <int KD, int ND, bool FFN1>
__global__ void __launch_bounds__(128, 2)
moe_gemm_h(const __half* __restrict__ Ah, const __half* __restrict__ Wh,
           const float* __restrict__ bias) {
    extern __shared__ char smem[];
    uint32_t smb = smem_u32(smem);

    int tid = threadIdx.x;
    int warp = tid >> 5, lane = tid & 31;
    int wm = warp & 1, wn = warp >> 1;
    int l15 = lane & 15, hi = lane >> 4;

    int e = blockIdx.y >> 6;
    int rt = blockIdx.y & 63;
    int seg0 = g_offsets[e], seg1 = g_offsets[e + 1];
    int row0 = seg0 + rt * 128;
    if (row0 >= seg1) return;
    int n0 = blockIdx.x * 128;

    // ---- A loader: 8 chunks/thread ----
    const __half* a_src[8];
    int a_bytes[8];
#pragma unroll
    for (int j = 0; j < 8; j++) {
        int idx = tid + 128 * j;
        int row = idx >> 3, c = idx & 7;
        int grow = row0 + row;
        bool v = grow < seg1;
        if (FFN1) {
            int pair = v ? g_list[grow] : 0;
            a_src[j] = Ah + (size_t)(pair >> 1) * KD + c * 8;
        } else {
            a_src[j] = Ah + (size_t)(v ? grow : row0) * KD + c * 8;
        }
        a_bytes[j] = v ? 16 : 0;
    }
    const __half* wbase = Wh + (size_t)e * KD * ND + n0;

    auto load_stage = [&](int s, int kt) {
        int k0 = kt * 64;
        uint32_t base = smb + s * 32768;
#pragma unroll
        for (int j = 0; j < 8; j++) {
            int idx = tid + 128 * j;
            int row = idx >> 3, c = idx & 7;
            uint32_t off = (uint32_t)row * 128 + (uint32_t)((c ^ (row & 7)) << 4);
            cp16(base + off, a_src[j] + k0, a_bytes[j]);
        }
#pragma unroll
        for (int j = 0; j < 8; j++) {
            int idx = tid + 128 * j;
            int k = idx >> 4, c = idx & 15;
            uint32_t off = 16384u + (uint32_t)k * 256 + (uint32_t)((c ^ (k & 7)) << 4);
            cp16(base + off, wbase + (size_t)(k0 + k) * ND + c * 8, 16);
        }
        asm volatile("cp.async.commit_group;");
    };

    float acc[4][8][4];
#pragma unroll
    for (int mi = 0; mi < 4; mi++)
#pragma unroll
        for (int ni = 0; ni < 8; ni++)
#pragma unroll
            for (int d = 0; d < 4; d++) acc[mi][ni][d] = 0.0f;

    constexpr int KT = KD / 64;
    load_stage(0, 0);
    load_stage(1, 1);

    for (int kt = 0; kt < KT; kt++) {
        if (kt + 1 < KT) asm volatile("cp.async.wait_group 1;");
        else             asm volatile("cp.async.wait_group 0;");
        __syncthreads();
        if (kt + 2 < KT) load_stage((kt + 2) % 3, kt + 2);

        uint32_t abase = smb + (kt % 3) * 32768;
        uint32_t bbase = abase + 16384;
#pragma unroll
        for (int ks = 0; ks < 4; ks++) {
            uint32_t a[4][4];
#pragma unroll
            for (int mi = 0; mi < 4; mi++) {
                int row = wm * 64 + mi * 16 + l15;
                uint32_t addr = abase + (uint32_t)row * 128 +
                                (uint32_t)(((ks * 2 + hi) ^ (row & 7)) << 4);
                ldsm4(a[mi], addr);
            }
            uint32_t b[4][4];
#pragma unroll
            for (int np = 0; np < 4; np++) {
                int krow = ks * 16 + l15;
                int c = wn * 8 + np * 2 + hi;
                uint32_t addr = bbase + (uint32_t)krow * 256 +
                                (uint32_t)((c ^ (krow & 7)) << 4);
                ldsm4t(b[np], addr);
            }
#pragma unroll
            for (int mi = 0; mi < 4; mi++)
#pragma unroll
                for (int np = 0; np < 4; np++) {
                    mma_f16(acc[mi][np * 2 + 0], a[mi], b[np] + 0);
                    mma_f16(acc[mi][np * 2 + 1], a[mi], b[np] + 2);
                }
        }
    }

    // ---- epilogue ----
    int r4 = lane >> 2, c2 = (lane & 3) * 2;
#pragma unroll
    for (int mi = 0; mi < 4; mi++) {
#pragma unroll
        for (int h = 0; h < 2; h++) {
            int grow = row0 + wm * 64 + mi * 16 + r4 + h * 8;
            if (grow < seg1) {
                if (FFN1) {
                    __half* orow = g_hidh + (size_t)grow * ND;
#pragma unroll
                    for (int ni = 0; ni < 8; ni++) {
                        int col = n0 + wn * 64 + ni * 8 + c2;
                        float2 bv = *(const float2*)(bias + (size_t)e * ND + col);
                        float v0 = gelu_exact(acc[mi][ni][h * 2 + 0] + bv.x);
                        float v1 = gelu_exact(acc[mi][ni][h * 2 + 1] + bv.y);
                        *(__half2*)(orow + col) = __floats2half2_rn(v0, v1);
                    }
                } else {
                    int pair = g_list[grow];
                    float wgt = g_topk_w[pair];
                    float* orow = g_contrib + (size_t)pair * ND;
#pragma unroll
                    for (int ni = 0; ni < 8; ni++) {
                        int col = n0 + wn * 64 + ni * 8 + c2;
                        float2 bv = *(const float2*)(bias + (size_t)e * ND + col);
                        float v0 = (acc[mi][ni][h * 2 + 0] + bv.x) * wgt;
                        float v1 = (acc[mi][ni][h * 2 + 1] + bv.y) * wgt;
                        *(float2*)(orow + col) = make_float2(v0, v1);
                    }
                }
            }
        }
    }
}

// ---------------- combine -----------------------------------------------------
__global__ void combine_kernel(float* __restrict__ out) {
    constexpr int H4 = HDIM / 4;
    size_t i = (size_t)blockIdx.x * blockDim.x + threadIdx.x;
    if (i < (size_t)TOK * H4) {
        size_t t = i / H4, h4 = i % H4;
        const float4* c = (const float4*)g_contrib;
        float4 a = c[(t * 2) * H4 + h4];
        float4 b = c[(t * 2 + 1) * H4 + h4];
        ((float4*)out)[i] = make_float4(a.x + b.x, a.y + b.y, a.z + b.z, a.w + b.w);
    }
}

// ---------------- launch --------------------------------------------------------
extern "C" void kernel_launch(void* const* d_in, const int* in_sizes, int n_in,
                              void* d_out, int out_size) {
    const float* x  = (const float*)d_in[0];
    const float* rw = (const float*)d_in[1];
    const float* w1 = (const float*)d_in[2];
    const float* b1 = (const float*)d_in[3];
    const float* w2 = (const float*)d_in[4];
    const float* b2 = (const float*)d_in[5];
    float* out = (float*)d_out;

    __half* xh;  cudaGetSymbolAddress((void**)&xh,  g_xh);
    __half* w1h; cudaGetSymbolAddress((void**)&w1h, g_w1h);
    __half* w2h; cudaGetSymbolAddress((void**)&w2h, g_w2h);
    __half* hid; cudaGetSymbolAddress((void**)&hid, g_hidh);

    constexpr int SMEM_BYTES = 3 * 32768;  // 98304
    cudaFuncSetAttribute(moe_gemm_h<HDIM, FDIM, true >,
                         cudaFuncAttributeMaxDynamicSharedMemorySize, SMEM_BYTES);
    cudaFuncSetAttribute(moe_gemm_h<FDIM, HDIM, false>,
                         cudaFuncAttributeMaxDynamicSharedMemorySize, SMEM_BYTES);

    // Lazily-created side stream + events (host handles only; reused so the
    // captured work is identical on every call).
    static cudaStream_t s_cvt = nullptr;
    static cudaEvent_t  ev_fork = nullptr, ev_w1 = nullptr, ev_w2 = nullptr;
    if (s_cvt == nullptr) {
        cudaStreamCreateWithFlags(&s_cvt, cudaStreamNonBlocking);
        cudaEventCreateWithFlags(&ev_fork, cudaEventDisableTiming);
        cudaEventCreateWithFlags(&ev_w1,   cudaEventDisableTiming);
        cudaEventCreateWithFlags(&ev_w2,   cudaEventDisableTiming);
    }

    size_t nx  = (size_t)TOK * HDIM / 8;
    size_t nw1 = (size_t)NE * HDIM * FDIM / 8;
    size_t nw2 = (size_t)NE * FDIM * HDIM / 8;

    // ---- fork: conversions on side stream ----
    cudaEventRecord(ev_fork, 0);
    cudaStreamWaitEvent(s_cvt, ev_fork, 0);
    cvt_half_kernel<<<(int)((nx  + 255) / 256), 256, 0, s_cvt>>>(x,  xh,  nx);
    cvt_half_kernel<<<(int)((nw1 + 255) / 256), 256, 0, s_cvt>>>(w1, w1h, nw1);
    cudaEventRecord(ev_w1, s_cvt);
    cvt_half_kernel<<<(int)((nw2 + 255) / 256), 256, 0, s_cvt>>>(w2, w2h, nw2);
    cudaEventRecord(ev_w2, s_cvt);

    // ---- main stream: router chain in parallel with conversions ----
    reset_kernel<<<1, 32>>>();
    router_kernel<<<TOK / 8, 256>>>(x, rw);
    scan_kernel<<<1, 32>>>();
    scatter_kernel<<<TOK / 256, 256>>>();

    cudaStreamWaitEvent(0, ev_w1, 0);   // xh + w1h ready
    moe_gemm_h<HDIM, FDIM, true ><<<dim3(FDIM / 128, NE * 64), 128, SMEM_BYTES>>>(xh,  w1h, b1);
    cudaStreamWaitEvent(0, ev_w2, 0);   // w2h ready (hidden under FFN1)
    moe_gemm_h<FDIM, HDIM, false><<<dim3(HDIM / 128, NE * 64), 128, SMEM_BYTES>>>(hid, w2h, b2);
    combine_kernel<<<(TOK * HDIM / 4) / 256, 256>>>(out);
}

// round 10
// speedup vs baseline: 1.2163x; 1.0012x over previous
#include <cuda_runtime.h>
#include <cuda_fp16.h>
#include <cstdint>

#define TOK   8192
#define HDIM  1024
#define FDIM  4096
#define NE    8

// ---------------- scratch (static device globals) ---------------------------
__device__ int    g_counts[NE];
__device__ int    g_offsets[NE + 1];
__device__ int    g_cursor[NE];
__device__ int    g_topk_i[TOK * 2];
__device__ float  g_topk_w[TOK * 2];
__device__ int    g_list[TOK * 2];
__device__ __half g_xh[(size_t)TOK * HDIM];            // x in fp16
__device__ __half g_w1h[(size_t)NE * HDIM * FDIM];     // w1 in fp16
__device__ __half g_w2h[(size_t)NE * FDIM * HDIM];     // w2 in fp16
__device__ __half g_hidh[(size_t)TOK * 2 * FDIM];      // gelu(x@w1+b1) fp16

// ---------------- PTX helpers ------------------------------------------------
__device__ __forceinline__ uint32_t smem_u32(const void* p) {
    uint32_t a;
    asm("{ .reg .u64 t; cvta.to.shared.u64 t, %1; cvt.u32.u64 %0, t; }" : "=r"(a) : "l"(p));
    return a;
}
__device__ __forceinline__ void cp16(uint32_t dst, const void* src, int bytes) {
    asm volatile("cp.async.cg.shared.global [%0], [%1], 16, %2;"
                 :: "r"(dst), "l"(src), "r"(bytes));
}
__device__ __forceinline__ void ldsm4(uint32_t* r, uint32_t addr) {
    asm volatile("ldmatrix.sync.aligned.m8n8.x4.shared.b16 {%0,%1,%2,%3}, [%4];"
                 : "=r"(r[0]), "=r"(r[1]), "=r"(r[2]), "=r"(r[3]) : "r"(addr));
}
__device__ __forceinline__ void ldsm4t(uint32_t* r, uint32_t addr) {
    asm volatile("ldmatrix.sync.aligned.m8n8.x4.trans.shared.b16 {%0,%1,%2,%3}, [%4];"
                 : "=r"(r[0]), "=r"(r[1]), "=r"(r[2]), "=r"(r[3]) : "r"(addr));
}
__device__ __forceinline__ void mma_f16(float* d, const uint32_t* a, const uint32_t* b) {
    asm volatile(
        "mma.sync.aligned.m16n8k16.row.col.f32.f16.f16.f32 "
        "{%0,%1,%2,%3}, {%4,%5,%6,%7}, {%8,%9}, {%0,%1,%2,%3};"
        : "+f"(d[0]), "+f"(d[1]), "+f"(d[2]), "+f"(d[3])
        : "r"(a[0]), "r"(a[1]), "r"(a[2]), "r"(a[3]), "r"(b[0]), "r"(b[1]));
}
__device__ __forceinline__ float gelu_exact(float v) {
    return 0.5f * v * (1.0f + erff(v * 0.70710678118654752f));
}

// ---------------- small kernels ----------------------------------------------
__global__ void reset_kernel() {
    if (threadIdx.x < NE) g_counts[threadIdx.x] = 0;
}

__global__ void zero_out_kernel(float* __restrict__ out, size_t n4) {
    size_t i = (size_t)blockIdx.x * blockDim.x + threadIdx.x;
    if (i < n4) ((float4*)out)[i] = make_float4(0.f, 0.f, 0.f, 0.f);
}

__global__ void cvt_half_kernel(const float* __restrict__ src, __half* __restrict__ dst,
                                size_t n8) {
    size_t i = (size_t)blockIdx.x * blockDim.x + threadIdx.x;
    if (i < n8) {
        float4 v0 = ((const float4*)src)[i * 2];
        float4 v1 = ((const float4*)src)[i * 2 + 1];
        __half2 h[4];
        h[0] = __floats2half2_rn(v0.x, v0.y);
        h[1] = __floats2half2_rn(v0.z, v0.w);
        h[2] = __floats2half2_rn(v1.x, v1.y);
        h[3] = __floats2half2_rn(v1.z, v1.w);
        ((uint4*)dst)[i] = *(uint4*)h;
    }
}

__global__ void router_kernel(const float* __restrict__ x, const float* __restrict__ rw) {
    __shared__ float srw[NE * HDIM];
    int tid = threadIdx.x;
    for (int i = tid; i < NE * HDIM; i += 256) srw[i] = rw[i];
    __syncthreads();
    int warp = tid >> 5, lane = tid & 31;
    int t = blockIdx.x * 8 + warp;
    if (t >= TOK) return;
    const float* xr = x + (size_t)t * HDIM;
    float acc[NE];
#pragma unroll
    for (int e = 0; e < NE; e++) acc[e] = 0.0f;
    for (int h = lane; h < HDIM; h += 32) {
        float xv = xr[h];
#pragma unroll
        for (int e = 0; e < NE; e++) acc[e] += xv * srw[e * HDIM + h];
    }
#pragma unroll
    for (int off = 16; off > 0; off >>= 1)
#pragma unroll
        for (int e = 0; e < NE; e++) acc[e] += __shfl_xor_sync(0xffffffffu, acc[e], off);
    if (lane == 0) {
        float mx = acc[0];
#pragma unroll
        for (int e = 1; e < NE; e++) mx = fmaxf(mx, acc[e]);
        float p[NE], s = 0.0f;
#pragma unroll
        for (int e = 0; e < NE; e++) { p[e] = expf(acc[e] - mx); s += p[e]; }
        float inv = 1.0f / s;
#pragma unroll
        for (int e = 0; e < NE; e++) p[e] *= inv;
        int i1 = 0;
#pragma unroll
        for (int e = 1; e < NE; e++) if (p[e] > p[i1]) i1 = e;
        int i2 = (i1 == 0) ? 1 : 0;
#pragma unroll
        for (int e = 0; e < NE; e++) if (e != i1 && p[e] > p[i2]) i2 = e;
        g_topk_i[t * 2 + 0] = i1; g_topk_w[t * 2 + 0] = p[i1];
        g_topk_i[t * 2 + 1] = i2; g_topk_w[t * 2 + 1] = p[i2];
        atomicAdd(&g_counts[i1], 1);
        atomicAdd(&g_counts[i2], 1);
    }
}

__global__ void scan_kernel() {
    if (threadIdx.x == 0) {
        int o = 0;
        g_offsets[0] = 0;
        for (int e = 0; e < NE; e++) {
            g_cursor[e] = o;
            o += g_counts[e];
            g_offsets[e + 1] = o;
        }
    }
}

__global__ void scatter_kernel() {
    int t = blockIdx.x * 256 + threadIdx.x;
    if (t < TOK) {
#pragma unroll
        for (int s = 0; s < 2; s++) {
            int e = g_topk_i[t * 2 + s];
            int pos = atomicAdd(&g_cursor[e], 1);
            g_list[pos] = t * 2 + s;
        }
    }
}

// ---------------- fp16 grouped GEMM (m16n8k16 + ldmatrix) --------------------
// Tile 128x128, BK=64, 128 threads = 4 warps (2Mx2N), warp tile 64x64.
// 3-stage cp.async pipeline, one __syncthreads per K-tile. (R4 hot loop.)
// FFN1 epilogue -> g_hidh (fp16). FFN2 epilogue -> atomicAdd into out:
// each out element receives exactly 2 adds from 0.0f; fp add is commutative,
// so the result is bit-deterministic regardless of arrival order.
template <int KD, int ND, bool FFN1>
__global__ void __launch_bounds__(128, 2)
moe_gemm_h(const __half* __restrict__ Ah, const __half* __restrict__ Wh,
           const float* __restrict__ bias, float* __restrict__ outp) {
    extern __shared__ char smem[];
    uint32_t smb = smem_u32(smem);

    int tid = threadIdx.x;
    int warp = tid >> 5, lane = tid & 31;
    int wm = warp & 1, wn = warp >> 1;
    int l15 = lane & 15, hi = lane >> 4;

    int e = blockIdx.y >> 6;
    int rt = blockIdx.y & 63;
    int seg0 = g_offsets[e], seg1 = g_offsets[e + 1];
    int row0 = seg0 + rt * 128;
    if (row0 >= seg1) return;
    int n0 = blockIdx.x * 128;

    // ---- A loader: 8 chunks/thread ----
    const __half* a_src[8];
    int a_bytes[8];
#pragma unroll
    for (int j = 0; j < 8; j++) {
        int idx = tid + 128 * j;
        int row = idx >> 3, c = idx & 7;
        int grow = row0 + row;
        bool v = grow < seg1;
        if (FFN1) {
            int pair = v ? g_list[grow] : 0;
            a_src[j] = Ah + (size_t)(pair >> 1) * KD + c * 8;
        } else {
            a_src[j] = Ah + (size_t)(v ? grow : row0) * KD + c * 8;
        }
        a_bytes[j] = v ? 16 : 0;
    }
    const __half* wbase = Wh + (size_t)e * KD * ND + n0;

    auto load_stage = [&](int s, int kt) {
        int k0 = kt * 64;
        uint32_t base = smb + s * 32768;
#pragma unroll
        for (int j = 0; j < 8; j++) {
            int idx = tid + 128 * j;
            int row = idx >> 3, c = idx & 7;
            uint32_t off = (uint32_t)row * 128 + (uint32_t)((c ^ (row & 7)) << 4);
            cp16(base + off, a_src[j] + k0, a_bytes[j]);
        }
#pragma unroll
        for (int j = 0; j < 8; j++) {
            int idx = tid + 128 * j;
            int k = idx >> 4, c = idx & 15;
            uint32_t off = 16384u + (uint32_t)k * 256 + (uint32_t)((c ^ (k & 7)) << 4);
            cp16(base + off, wbase + (size_t)(k0 + k) * ND + c * 8, 16);
        }
        asm volatile("cp.async.commit_group;");
    };

    float acc[4][8][4];
#pragma unroll
    for (int mi = 0; mi < 4; mi++)
#pragma unroll
        for (int ni = 0; ni < 8; ni++)
#pragma unroll
            for (int d = 0; d < 4; d++) acc[mi][ni][d] = 0.0f;

    constexpr int KT = KD / 64;
    load_stage(0, 0);
    load_stage(1, 1);

    for (int kt = 0; kt < KT; kt++) {
        if (kt + 1 < KT) asm volatile("cp.async.wait_group 1;");
        else             asm volatile("cp.async.wait_group 0;");
        __syncthreads();
        if (kt + 2 < KT) load_stage((kt + 2) % 3, kt + 2);

        uint32_t abase = smb + (kt % 3) * 32768;
        uint32_t bbase = abase + 16384;
#pragma unroll
        for (int ks = 0; ks < 4; ks++) {
            uint32_t a[4][4];
#pragma unroll
            for (int mi = 0; mi < 4; mi++) {
                int row = wm * 64 + mi * 16 + l15;
                uint32_t addr = abase + (uint32_t)row * 128 +
                                (uint32_t)(((ks * 2 + hi) ^ (row & 7)) << 4);
                ldsm4(a[mi], addr);
            }
            uint32_t b[4][4];
#pragma unroll
            for (int np = 0; np < 4; np++) {
                int krow = ks * 16 + l15;
                int c = wn * 8 + np * 2 + hi;
                uint32_t addr = bbase + (uint32_t)krow * 256 +
                                (uint32_t)((c ^ (krow & 7)) << 4);
                ldsm4t(b[np], addr);
            }
#pragma unroll
            for (int mi = 0; mi < 4; mi++)
#pragma unroll
                for (int np = 0; np < 4; np++) {
                    mma_f16(acc[mi][np * 2 + 0], a[mi], b[np] + 0);
                    mma_f16(acc[mi][np * 2 + 1], a[mi], b[np] + 2);
                }
        }
    }

    // ---- epilogue ----
    int r4 = lane >> 2, c2 = (lane & 3) * 2;
#pragma unroll
    for (int mi = 0; mi < 4; mi++) {
#pragma unroll
        for (int h = 0; h < 2; h++) {
            int grow = row0 + wm * 64 + mi * 16 + r4 + h * 8;
            if (grow < seg1) {
                if (FFN1) {
                    __half* orow = g_hidh + (size_t)grow * ND;
#pragma unroll
                    for (int ni = 0; ni < 8; ni++) {
                        int col = n0 + wn * 64 + ni * 8 + c2;
                        float2 bv = *(const float2*)(bias + (size_t)e * ND + col);
                        float v0 = gelu_exact(acc[mi][ni][h * 2 + 0] + bv.x);
                        float v1 = gelu_exact(acc[mi][ni][h * 2 + 1] + bv.y);
                        *(__half2*)(orow + col) = __floats2half2_rn(v0, v1);
                    }
                } else {
                    int pair = g_list[grow];
                    float wgt = g_topk_w[pair];
                    float* orow = outp + (size_t)(pair >> 1) * ND;
#pragma unroll
                    for (int ni = 0; ni < 8; ni++) {
                        int col = n0 + wn * 64 + ni * 8 + c2;
                        float2 bv = *(const float2*)(bias + (size_t)e * ND + col);
                        float v0 = (acc[mi][ni][h * 2 + 0] + bv.x) * wgt;
                        float v1 = (acc[mi][ni][h * 2 + 1] + bv.y) * wgt;
                        atomicAdd(orow + col, v0);
                        atomicAdd(orow + col + 1, v1);
                    }
                }
            }
        }
    }
}

// ---------------- launch --------------------------------------------------------
extern "C" void kernel_launch(void* const* d_in, const int* in_sizes, int n_in,
                              void* d_out, int out_size) {
    const float* x  = (const float*)d_in[0];
    const float* rw = (const float*)d_in[1];
    const float* w1 = (const float*)d_in[2];
    const float* b1 = (const float*)d_in[3];
    const float* w2 = (const float*)d_in[4];
    const float* b2 = (const float*)d_in[5];
    float* out = (float*)d_out;

    __half* xh;  cudaGetSymbolAddress((void**)&xh,  g_xh);
    __half* w1h; cudaGetSymbolAddress((void**)&w1h, g_w1h);
    __half* w2h; cudaGetSymbolAddress((void**)&w2h, g_w2h);
    __half* hid; cudaGetSymbolAddress((void**)&hid, g_hidh);

    constexpr int SMEM_BYTES = 3 * 32768;  // 98304
    cudaFuncSetAttribute(moe_gemm_h<HDIM, FDIM, true >,
                         cudaFuncAttributeMaxDynamicSharedMemorySize, SMEM_BYTES);
    cudaFuncSetAttribute(moe_gemm_h<FDIM, HDIM, false>,
                         cudaFuncAttributeMaxDynamicSharedMemorySize, SMEM_BYTES);

    // Lazily-created side stream + events (host handles only; reused so the
    // captured work is identical on every call).
    static cudaStream_t s_cvt = nullptr;
    static cudaEvent_t  ev_fork = nullptr, ev_w1 = nullptr, ev_w2 = nullptr;
    if (s_cvt == nullptr) {
        cudaStreamCreateWithFlags(&s_cvt, cudaStreamNonBlocking);
        cudaEventCreateWithFlags(&ev_fork, cudaEventDisableTiming);
        cudaEventCreateWithFlags(&ev_w1,   cudaEventDisableTiming);
        cudaEventCreateWithFlags(&ev_w2,   cudaEventDisableTiming);
    }

    size_t nx  = (size_t)TOK * HDIM / 8;
    size_t nw1 = (size_t)NE * HDIM * FDIM / 8;
    size_t nw2 = (size_t)NE * FDIM * HDIM / 8;
    size_t no4 = (size_t)TOK * HDIM / 4;

    // ---- fork: conversions + output zeroing on side stream ----
    cudaEventRecord(ev_fork, 0);
    cudaStreamWaitEvent(s_cvt, ev_fork, 0);
    zero_out_kernel<<<(int)((no4 + 255) / 256), 256, 0, s_cvt>>>(out, no4);
    cvt_half_kernel<<<(int)((nx  + 255) / 256), 256, 0, s_cvt>>>(x,  xh,  nx);
    cvt_half_kernel<<<(int)((nw1 + 255) / 256), 256, 0, s_cvt>>>(w1, w1h, nw1);
    cudaEventRecord(ev_w1, s_cvt);
    cvt_half_kernel<<<(int)((nw2 + 255) / 256), 256, 0, s_cvt>>>(w2, w2h, nw2);
    cudaEventRecord(ev_w2, s_cvt);

    // ---- main stream: router chain in parallel with conversions ----
    reset_kernel<<<1, 32>>>();
    router_kernel<<<TOK / 8, 256>>>(x, rw);
    scan_kernel<<<1, 32>>>();
    scatter_kernel<<<TOK / 256, 256>>>();

    cudaStreamWaitEvent(0, ev_w1, 0);   // xh + w1h ready
    moe_gemm_h<HDIM, FDIM, true ><<<dim3(FDIM / 128, NE * 64), 128, SMEM_BYTES>>>(xh,  w1h, b1, out);
    cudaStreamWaitEvent(0, ev_w2, 0);   // w2h + zeroed out ready (hidden under FFN1)
    moe_gemm_h<FDIM, HDIM, false><<<dim3(HDIM / 128, NE * 64), 128, SMEM_BYTES>>>(hid, w2h, b2, out);
}